// round 4
// baseline (speedup 1.0000x reference)
#include <cuda_runtime.h>
#include <math.h>

#define NIMG   32
#define HW     1024
#define NB     128
#define NCTA   (NIMG * NB)
#define NVALS  131072.0   // 128*128*8 values per band per image

// Band id per DCT coefficient flat index (k*8+l), from the JPEG zigzag of
// the reference's _zigzag_flat(8). Constant indexing in fully unrolled loops
// => folded to immediates.
__device__ constexpr int BAND_OF[64] = {
    0,0,0,0,1,1,3,3,
    0,0,0,1,2,3,3,5,
    0,1,1,2,3,3,5,5,
    1,1,2,3,3,5,5,6,
    1,2,2,4,4,5,6,6,
    2,2,4,4,5,6,6,7,
    2,4,4,5,6,7,7,7,
    4,4,6,6,7,7,7,7
};

__device__ float g_part[NCTA * 16];
__device__ unsigned int g_cnt[NIMG];   // zero-init; advances by exactly NB per image per launch

// 8-point DCT-II with hardcoded immediates (matches _dct_matrix(8) in f32).
__device__ __forceinline__ void dct8(const float x[8], float o[8])
{
    float s0 = x[0] + x[7], s1 = x[1] + x[6], s2 = x[2] + x[5], s3 = x[3] + x[4];
    float d0 = x[0] - x[7], d1 = x[1] - x[6], d2 = x[2] - x[5], d3 = x[3] - x[4];
    float f0 = s0 + s3, f1 = s1 + s2;
    float e0 = s0 - s3, e1 = s1 - s2;

    o[0] = 0.35355339f * (f0 + f1);
    o[4] = 0.35355339f * (f0 - f1);
    o[2] = fmaf(0.46193977f, e0,  0.19134172f * e1);
    o[6] = fmaf(0.19134172f, e0, -0.46193977f * e1);

    o[1] = fmaf(0.49039264f, d0, fmaf( 0.41573481f, d1, fmaf( 0.27778512f, d2,  0.09754516f * d3)));
    o[3] = fmaf(0.41573481f, d0, fmaf(-0.09754516f, d1, fmaf(-0.49039264f, d2, -0.27778512f * d3)));
    o[5] = fmaf(0.27778512f, d0, fmaf(-0.49039264f, d1, fmaf( 0.09754516f, d2,  0.41573481f * d3)));
    o[7] = fmaf(0.09754516f, d0, fmaf(-0.27778512f, d1, fmaf( 0.41573481f, d2, -0.49039264f * d3)));
}

__global__ void __launch_bounds__(128)
dct_stats_fused_kernel(const float* __restrict__ img,
                       const float* __restrict__ W,
                       const float* __restrict__ bias,
                       float* __restrict__ out)
{
    int g   = blockIdx.x;          // 4096 CTAs = 32 images * 128 strips
    int b   = g >> 7;              // image
    int by  = g & 127;             // 8-row strip
    int tid = threadIdx.x;         // block-column 0..127

    const float* base = img + (size_t)b * 3u * HW * HW + (size_t)(by * 8) * HW + tid * 8;

    // luma weights with x255 folded in (lum.max() <= 1 provably holds)
    const float wr = 0.299f * 255.0f;
    const float wg = 0.587f * 255.0f;
    const float wb = 0.114f * 255.0f;

    float T[8][8];   // stage-1 output: T[i][l]

#pragma unroll
    for (int i = 0; i < 8; i++) {
        const float* p = base + i * HW;
        float4 r0 = *(const float4*)(p);
        float4 r1 = *(const float4*)(p + 4);
        float4 g0 = *(const float4*)(p + HW * HW);
        float4 g1 = *(const float4*)(p + HW * HW + 4);
        float4 c0 = *(const float4*)(p + 2 * HW * HW);
        float4 c1 = *(const float4*)(p + 2 * HW * HW + 4);

        float x[8];
        x[0] = fmaf(wr, r0.x, fmaf(wg, g0.x, wb * c0.x));
        x[1] = fmaf(wr, r0.y, fmaf(wg, g0.y, wb * c0.y));
        x[2] = fmaf(wr, r0.z, fmaf(wg, g0.z, wb * c0.z));
        x[3] = fmaf(wr, r0.w, fmaf(wg, g0.w, wb * c0.w));
        x[4] = fmaf(wr, r1.x, fmaf(wg, g1.x, wb * c1.x));
        x[5] = fmaf(wr, r1.y, fmaf(wg, g1.y, wb * c1.y));
        x[6] = fmaf(wr, r1.z, fmaf(wg, g1.z, wb * c1.z));
        x[7] = fmaf(wr, r1.w, fmaf(wg, g1.w, wb * c1.w));

        float u[8];
        dct8(x, u);
#pragma unroll
        for (int l = 0; l < 8; l++) T[i][l] = u[l];
    }

    float bs[8] = {0,0,0,0,0,0,0,0};
    float bq[8] = {0,0,0,0,0,0,0,0};

#pragma unroll
    for (int l = 0; l < 8; l++) {
        float col[8], y[8];
#pragma unroll
        for (int i = 0; i < 8; i++) col[i] = T[i][l];
        dct8(col, y);
#pragma unroll
        for (int k = 0; k < 8; k++) {
            float a = fabsf(y[k]);
            int band = BAND_OF[k * 8 + l];   // compile-time constant
            bs[band] += a;
            bq[band] = fmaf(a, a, bq[band]);
        }
    }

    // warp tree-reduce the 16 accumulators
#pragma unroll
    for (int m = 0; m < 8; m++) {
#pragma unroll
        for (int off = 16; off > 0; off >>= 1) {
            bs[m] += __shfl_down_sync(0xFFFFFFFFu, bs[m], off);
            bq[m] += __shfl_down_sync(0xFFFFFFFFu, bq[m], off);
        }
    }

    __shared__ float red[4][16];
    __shared__ unsigned int s_last;
    int wid = tid >> 5, lane = tid & 31;
    if (lane == 0) {
#pragma unroll
        for (int m = 0; m < 8; m++) {
            red[wid][m]     = bs[m];
            red[wid][8 + m] = bq[m];
        }
    }
    __syncthreads();
    if (tid < 16) {
        float v = red[0][tid] + red[1][tid] + red[2][tid] + red[3][tid];
        g_part[g * 16 + tid] = v;
    }
    __syncthreads();

    // Arrival protocol: make partials visible, then count arrivals for this image.
    if (tid == 0) {
        __threadfence();
        unsigned int old = atomicAdd(&g_cnt[b], 1u);
        s_last = ((old & (NB - 1u)) == (NB - 1u)) ? 1u : 0u;
    }
    __syncthreads();
    if (!s_last) return;

    // ---- This CTA is the 128th arriver for image b: finalize it. ----
    // Reduce 128 strips x 16 slots in a FIXED order (bitwise deterministic).
    __shared__ float sh[4][16];
    __shared__ float raw[16];

    int s   = tid & 15;       // slot
    int grp = tid >> 4;       // 8 groups x 16 strips each

    const float* p = g_part + (size_t)b * NB * 16 + grp * 16 * 16 + s;
    float acc = 0.0f;
#pragma unroll
    for (int c = 0; c < 16; c++) acc += p[c * 16];

    // fold group pairs within each warp (lanes 0-15 <- +lanes 16-31)
    acc += __shfl_down_sync(0xFFFFFFFFu, acc, 16);
    if (lane < 16) sh[wid][s] = acc;
    __syncthreads();

    if (tid < 16) {
        float tot = sh[0][tid] + sh[1][tid] + sh[2][tid] + sh[3][tid];
        sh[0][tid] = tot;
    }
    __syncthreads();

    if (tid < 8) {
        double sum = (double)sh[0][tid];
        double sq  = (double)sh[0][tid + 8];
        double mean = sum / NVALS;
        double var  = (sq - NVALS * mean * mean) / (NVALS - 1.0);
        if (var < 0.0) var = 0.0;
        raw[tid]     = (float)mean;
        raw[tid + 8] = (float)sqrt(var);
    }
    __syncthreads();

    // 16 -> 512 GEMV for this image (128 threads x 4 outputs)
#pragma unroll
    for (int q = 0; q < 4; q++) {
        int f = tid + q * 128;
        float acc2 = bias[f];
#pragma unroll
        for (int j = 0; j < 16; j++)
            acc2 = fmaf(raw[j], W[f * 16 + j], acc2);
        out[b * 512 + f] = acc2;
    }
}

extern "C" void kernel_launch(void* const* d_in, const int* in_sizes, int n_in,
                              void* d_out, int out_size)
{
    const float* img  = (const float*)d_in[0];   // [32,3,1024,1024] f32
    // d_in[1] (dct_matrix) baked in as immediates; d_in[2] (zigzag) baked into BAND_OF
    const float* W    = (const float*)d_in[3];   // [512,16] f32
    const float* bias = (const float*)d_in[4];   // [512] f32
    float* out = (float*)d_out;                  // [32,512] f32

    dct_stats_fused_kernel<<<NCTA, 128>>>(img, W, bias, out);
}

// round 5
// speedup vs baseline: 1.0876x; 1.0876x over previous
#include <cuda_runtime.h>
#include <math.h>

#define NIMG   32
#define HW     1024
#define NB     128
#define NCTA2  (NIMG * NB * 2)      // 8192 CTAs, each = half a strip (64 blocks)
#define ARRIV  256                  // CTAs per image
#define NVALS  131072.0             // 128*128*8 values per band per image

__device__ constexpr int BAND_OF[64] = {
    0,0,0,0,1,1,3,3,
    0,0,0,1,2,3,3,5,
    0,1,1,2,3,3,5,5,
    1,1,2,3,3,5,5,6,
    1,2,2,4,4,5,6,6,
    2,2,4,4,5,6,6,7,
    2,4,4,5,6,7,7,7,
    4,4,6,6,7,7,7,7
};

__device__ float g_part[NCTA2 * 16];
__device__ unsigned int g_cnt[NIMG];   // zero-init; +256 per image per launch

// 8-point DCT-II, immediates match _dct_matrix(8) in f32.
__device__ __forceinline__ void dct8(const float x[8], float o[8])
{
    float s0 = x[0] + x[7], s1 = x[1] + x[6], s2 = x[2] + x[5], s3 = x[3] + x[4];
    float d0 = x[0] - x[7], d1 = x[1] - x[6], d2 = x[2] - x[5], d3 = x[3] - x[4];
    float f0 = s0 + s3, f1 = s1 + s2;
    float e0 = s0 - s3, e1 = s1 - s2;
    o[0] = 0.35355339f * (f0 + f1);
    o[4] = 0.35355339f * (f0 - f1);
    o[2] = fmaf(0.46193977f, e0,  0.19134172f * e1);
    o[6] = fmaf(0.19134172f, e0, -0.46193977f * e1);
    o[1] = fmaf(0.49039264f, d0, fmaf( 0.41573481f, d1, fmaf( 0.27778512f, d2,  0.09754516f * d3)));
    o[3] = fmaf(0.41573481f, d0, fmaf(-0.09754516f, d1, fmaf(-0.49039264f, d2, -0.27778512f * d3)));
    o[5] = fmaf(0.27778512f, d0, fmaf(-0.49039264f, d1, fmaf( 0.09754516f, d2,  0.41573481f * d3)));
    o[7] = fmaf(0.09754516f, d0, fmaf(-0.27778512f, d1, fmaf( 0.41573481f, d2, -0.49039264f * d3)));
}

__global__ void __launch_bounds__(128, 7)
dct_stats_fused_kernel(const float* __restrict__ img,
                       const float* __restrict__ W,
                       const float* __restrict__ bias,
                       float* __restrict__ out)
{
    int g    = blockIdx.x;            // 8192 = 32 img * 128 strips * 2 halves
    int b    = g >> 8;                // image
    int rest = g & 255;
    int by   = rest >> 1;             // strip (8-row band)
    int half = rest & 1;              // which 64-block half of the strip
    int tid  = threadIdx.x;
    int p    = tid & 1;               // 0: rows 0-3 (+ band-sum), 1: rows 4-7 (+ band-sumsq)
    int c    = tid >> 1;              // block index within half-strip (0..63)
    int bx   = half * 64 + c;         // block-column 0..127
    bool pod = (p != 0);

    const float* base = img + (size_t)b * 3u * HW * HW
                            + (size_t)(by * 8 + p * 4) * HW + bx * 8;

    const float wr = 0.299f * 255.0f;
    const float wg = 0.587f * 255.0f;
    const float wb = 0.114f * 255.0f;

    float T[4][8];   // this thread's 4 row-transformed rows

#pragma unroll
    for (int j = 0; j < 4; j++) {
        const float* q = base + j * HW;
        float4 r0 = *(const float4*)(q);
        float4 r1 = *(const float4*)(q + 4);
        float4 g0 = *(const float4*)(q + HW * HW);
        float4 g1 = *(const float4*)(q + HW * HW + 4);
        float4 c0 = *(const float4*)(q + 2 * HW * HW);
        float4 c1 = *(const float4*)(q + 2 * HW * HW + 4);

        float x[8];
        x[0] = fmaf(wr, r0.x, fmaf(wg, g0.x, wb * c0.x));
        x[1] = fmaf(wr, r0.y, fmaf(wg, g0.y, wb * c0.y));
        x[2] = fmaf(wr, r0.z, fmaf(wg, g0.z, wb * c0.z));
        x[3] = fmaf(wr, r0.w, fmaf(wg, g0.w, wb * c0.w));
        x[4] = fmaf(wr, r1.x, fmaf(wg, g1.x, wb * c1.x));
        x[5] = fmaf(wr, r1.y, fmaf(wg, g1.y, wb * c1.y));
        x[6] = fmaf(wr, r1.z, fmaf(wg, g1.z, wb * c1.z));
        x[7] = fmaf(wr, r1.w, fmaf(wg, g1.w, wb * c1.w));

        dct8(x, T[j]);
    }

    // parity-split accumulators: even lanes Sum|a|, odd lanes Sum a^2
    float acc[8] = {0,0,0,0,0,0,0,0};

#pragma unroll
    for (int l = 0; l < 8; l++) {
        // exchange this column's half with the partner thread
        float o0 = __shfl_xor_sync(0xFFFFFFFFu, T[0][l], 1);
        float o1 = __shfl_xor_sync(0xFFFFFFFFu, T[1][l], 1);
        float o2 = __shfl_xor_sync(0xFFFFFFFFu, T[2][l], 1);
        float o3 = __shfl_xor_sync(0xFFFFFFFFu, T[3][l], 1);

        // col[i] (i<4) and col[7-i]: branchless operand select by parity
        // even lane: ua_i = T[i][l],  ub_i = o[3-i]
        // odd  lane: ua_i = o[i],     ub_i = T[3-i][l]
        float ua0 = pod ? o0 : T[0][l], ub0 = pod ? T[3][l] : o3;
        float ua1 = pod ? o1 : T[1][l], ub1 = pod ? T[2][l] : o2;
        float ua2 = pod ? o2 : T[2][l], ub2 = pod ? T[1][l] : o1;
        float ua3 = pod ? o3 : T[3][l], ub3 = pod ? T[0][l] : o0;

        float s0 = ua0 + ub0, s1 = ua1 + ub1, s2 = ua2 + ub2, s3 = ua3 + ub3;
        float d0 = ua0 - ub0, d1 = ua1 - ub1, d2 = ua2 - ub2, d3 = ua3 - ub3;

        float f0 = s0 + s3, f1 = s1 + s2;
        float e0 = s0 - s3, e1 = s1 - s2;

        float y[8];
        y[0] = 0.35355339f * (f0 + f1);
        y[4] = 0.35355339f * (f0 - f1);
        y[2] = fmaf(0.46193977f, e0,  0.19134172f * e1);
        y[6] = fmaf(0.19134172f, e0, -0.46193977f * e1);
        y[1] = fmaf(0.49039264f, d0, fmaf( 0.41573481f, d1, fmaf( 0.27778512f, d2,  0.09754516f * d3)));
        y[3] = fmaf(0.41573481f, d0, fmaf(-0.09754516f, d1, fmaf(-0.49039264f, d2, -0.27778512f * d3)));
        y[5] = fmaf(0.27778512f, d0, fmaf(-0.49039264f, d1, fmaf( 0.09754516f, d2,  0.41573481f * d3)));
        y[7] = fmaf(0.09754516f, d0, fmaf(-0.27778512f, d1, fmaf( 0.41573481f, d2, -0.49039264f * d3)));

#pragma unroll
        for (int k = 0; k < 8; k++) {
            float a = fabsf(y[k]);
            float w2 = pod ? a : 1.0f;          // even: accumulate |a|; odd: a^2
            acc[BAND_OF[k * 8 + l]] = fmaf(a, w2, acc[BAND_OF[k * 8 + l]]);
        }
    }

    // warp reduce with even offsets only => parities never mix.
    // lane0 ends with Sum over even lanes (band sums), lane1 with odd (sumsqs).
#pragma unroll
    for (int m = 0; m < 8; m++) {
#pragma unroll
        for (int off = 16; off >= 2; off >>= 1)
            acc[m] += __shfl_down_sync(0xFFFFFFFFu, acc[m], off);
    }

    __shared__ float red[4][16];
    __shared__ unsigned int s_last;
    int wid = tid >> 5, lane = tid & 31;
    if (lane == 0) {
#pragma unroll
        for (int m = 0; m < 8; m++) red[wid][m] = acc[m];
    }
    if (lane == 1) {
#pragma unroll
        for (int m = 0; m < 8; m++) red[wid][8 + m] = acc[m];
    }
    __syncthreads();
    if (tid < 16) {
        float v = red[0][tid] + red[1][tid] + red[2][tid] + red[3][tid];
        g_part[g * 16 + tid] = v;
    }
    __syncthreads();

    if (tid == 0) {
        __threadfence();
        unsigned int old = atomicAdd(&g_cnt[b], 1u);
        s_last = ((old & (ARRIV - 1u)) == (ARRIV - 1u)) ? 1u : 0u;
    }
    __syncthreads();
    if (!s_last) return;

    // ---- last arriver for image b: reduce 256 CTA partials, stats, GEMV ----
    __shared__ float sh[4][16];
    __shared__ float raw[16];

    int s   = tid & 15;
    int grp = tid >> 4;       // 8 groups x 32 partials each

    const float* pp = g_part + (size_t)b * ARRIV * 16 + grp * 32 * 16 + s;
    float a2 = 0.0f;
#pragma unroll
    for (int cc = 0; cc < 32; cc++) a2 += pp[cc * 16];

    a2 += __shfl_down_sync(0xFFFFFFFFu, a2, 16);   // fold the 2 groups per warp
    if (lane < 16) sh[wid][s] = a2;
    __syncthreads();

    if (tid < 16) {
        float tot = sh[0][tid] + sh[1][tid] + sh[2][tid] + sh[3][tid];
        sh[0][tid] = tot;
    }
    __syncthreads();

    if (tid < 8) {
        double sum = (double)sh[0][tid];
        double sq  = (double)sh[0][tid + 8];
        double mean = sum / NVALS;
        double var  = (sq - NVALS * mean * mean) / (NVALS - 1.0);
        if (var < 0.0) var = 0.0;
        raw[tid]     = (float)mean;
        raw[tid + 8] = (float)sqrt(var);
    }
    __syncthreads();

#pragma unroll
    for (int q = 0; q < 4; q++) {
        int f = tid + q * 128;
        float acc2 = bias[f];
#pragma unroll
        for (int j = 0; j < 16; j++)
            acc2 = fmaf(raw[j], W[f * 16 + j], acc2);
        out[b * 512 + f] = acc2;
    }
}

extern "C" void kernel_launch(void* const* d_in, const int* in_sizes, int n_in,
                              void* d_out, int out_size)
{
    const float* img  = (const float*)d_in[0];   // [32,3,1024,1024] f32
    // d_in[1] (dct_matrix) baked as immediates; d_in[2] (zigzag) baked into BAND_OF
    const float* W    = (const float*)d_in[3];   // [512,16] f32
    const float* bias = (const float*)d_in[4];   // [512] f32
    float* out = (float*)d_out;                  // [32,512] f32

    dct_stats_fused_kernel<<<NCTA2, 128>>>(img, W, bias, out);
}